// round 1
// baseline (speedup 1.0000x reference)
#include <cuda_runtime.h>

#define NB 64
#define MB 128
#define LB 8192
#define DB 64
#define HOURS_C 168

#define LDJ 65     // padded row stride for joint/q/k/v (bank-conflict-free)
#define LDSC 132   // padded row stride for scores

// scratch (no runtime allocation allowed)
__device__ float g_rowsum[LB];
__device__ float g_X[(size_t)NB * MB * DB];

// ---------------------------------------------------------------------------
// Kernel 1: row sums of mat2s (L x L)  -> g_rowsum[l] = sum_j mat2s[l, j]
// ---------------------------------------------------------------------------
__global__ __launch_bounds__(256) void rowsum_kernel(const float* __restrict__ mat2s) {
    int l = blockIdx.x;
    const float4* row = (const float4*)(mat2s + (size_t)l * LB);
    float s = 0.f;
#pragma unroll
    for (int i = threadIdx.x; i < LB / 4; i += 256) {
        float4 v = row[i];
        s += v.x + v.y + v.z + v.w;
    }
    __shared__ float red[8];
#pragma unroll
    for (int o = 16; o; o >>= 1) s += __shfl_down_sync(~0u, s, o);
    if ((threadIdx.x & 31) == 0) red[threadIdx.x >> 5] = s;
    __syncthreads();
    if (threadIdx.x < 8) {
        s = red[threadIdx.x];
#pragma unroll
        for (int o = 4; o; o >>= 1) s += __shfl_down_sync(0xffu, s, o);
        if (threadIdx.x == 0) g_rowsum[l] = s;
    }
}

// ---------------------------------------------------------------------------
// Kernel 2: per-batch attention. One CTA per n (64 CTAs, 256 threads).
// Produces g_X[n,m,d] = self_attn[n,m,d] * delta2_sum[n,m,d]
// ---------------------------------------------------------------------------
extern __shared__ float sm_attn[];

__global__ __launch_bounds__(256) void attn_kernel(
    const int*   __restrict__ traj,
    const float* __restrict__ mat1,
    const float* __restrict__ vec,
    const int*   __restrict__ traj_len,
    const float* __restrict__ emb_t,
    const float* __restrict__ emb_l,
    const float* __restrict__ emb_u,
    const float* __restrict__ emb_su,
    const float* __restrict__ emb_sl,
    const float* __restrict__ emb_tu,
    const float* __restrict__ emb_tl,
    const float* __restrict__ Wq,
    const float* __restrict__ Wk,
    const float* __restrict__ Wv)
{
    const int n   = blockIdx.x;
    const int tid = threadIdx.x;

    float* joint = sm_attn;                  // 128*65
    float* q     = joint + MB * LDJ;
    float* k     = q + MB * LDJ;
    float* v     = k + MB * LDJ;
    float* sc    = v + MB * LDJ;             // 128*132 (also W staging)
    float* Ws    = sc;                       // 64*65 temp, aliases sc
    float* scal  = sc + MB * LDSC;           // 8 scalars

    const int len = traj_len[n];

    // scalar embedding sums: scal[which*2+row], which: 0=sl 1=su 2=tl 3=tu
    if (tid < 8) {
        int which = tid >> 1, row = tid & 1;
        const float* e = (which == 0) ? emb_sl : (which == 1) ? emb_su
                       : (which == 2) ? emb_tl : emb_tu;
        float s = 0.f;
#pragma unroll
        for (int d = 0; d < DB; d++) s += e[row * DB + d];
        scal[tid] = s;
    }

    // joint = emb_t[time] + emb_l[loc] + emb_u[user]
    for (int i = tid; i < MB * DB; i += 256) {
        int m = i >> 6, d = i & 63;
        int u   = traj[(n * MB + m) * 3 + 0];
        int loc = traj[(n * MB + m) * 3 + 1];
        int t   = traj[(n * MB + m) * 3 + 2];
        int ti  = (t - 1) % HOURS_C + 1;
        joint[m * LDJ + d] = emb_t[ti * DB + d] + emb_l[loc * DB + d] + emb_u[u * DB + d];
    }
    __syncthreads();

    // q = joint @ Wq^T ; k = joint @ Wk^T ; v = joint @ Wv^T
    const float* Wmats[3] = {Wq, Wk, Wv};
    float* outs[3] = {q, k, v};
#pragma unroll 1
    for (int w = 0; w < 3; w++) {
        for (int i = tid; i < DB * DB; i += 256)
            Ws[(i >> 6) * LDJ + (i & 63)] = Wmats[w][i];
        __syncthreads();
        for (int i = tid; i < MB * DB; i += 256) {
            int m = i >> 6, d = i & 63;
            float acc = 0.f;
#pragma unroll
            for (int j = 0; j < DB; j++)
                acc += joint[m * LDJ + j] * Ws[d * LDJ + j];
            outs[w][m * LDJ + d] = acc;
        }
        __syncthreads();
    }

    // scores[m][p] = q[m].k[p] + delta_sum(m,p)   (2 threads per m, 64 p each)
    {
        int m = tid >> 1, half = tid & 1;
        bool vm = m < len;
        float qreg[DB];
#pragma unroll
        for (int j = 0; j < DB; j++) qreg[j] = q[m * LDJ + j];
        float s0 = scal[0], s1 = scal[1], s2 = scal[2], s3 = scal[3];
        float s4 = scal[4], s5 = scal[5], s6 = scal[6], s7 = scal[7];
#pragma unroll 2
        for (int pp = 0; pp < 64; pp++) {
            int p = half * 64 + pp;
            float acc = 0.f;
#pragma unroll
            for (int j = 0; j < DB; j++) acc += qreg[j] * k[p * LDJ + j];
            bool msk = vm && (p < len);
            float2 dd = ((const float2*)mat1)[(size_t)(n * MB + m) * MB + p];
            float ds = dd.x, dt = dd.y;
            float ssl = msk ? s1 : s0;
            float ssu = msk ? s3 : s2;
            float stl = msk ? s5 : s4;
            float stu = msk ? s7 : s6;
            float delta = (ssl * (100.0f - ds) + ssu * ds) * 0.01f
                        + (stl * (500.0f - dt) + stu * dt) * 0.002f;
            sc[m * LDSC + p] = acc + delta;
        }
    }
    __syncthreads();

    // softmax over p (full row), then multiply by ragged mask
    {
        int wid = tid >> 5, lane = tid & 31;
        for (int m2 = wid; m2 < MB; m2 += 8) {
            float v0 = sc[m2 * LDSC + lane];
            float v1 = sc[m2 * LDSC + lane + 32];
            float v2 = sc[m2 * LDSC + lane + 64];
            float v3 = sc[m2 * LDSC + lane + 96];
            float mx = fmaxf(fmaxf(v0, v1), fmaxf(v2, v3));
#pragma unroll
            for (int o = 16; o; o >>= 1) mx = fmaxf(mx, __shfl_xor_sync(~0u, mx, o));
            float e0 = __expf(v0 - mx), e1 = __expf(v1 - mx);
            float e2 = __expf(v2 - mx), e3 = __expf(v3 - mx);
            float sum = e0 + e1 + e2 + e3;
#pragma unroll
            for (int o = 16; o; o >>= 1) sum += __shfl_xor_sync(~0u, sum, o);
            float inv = 1.0f / sum;
            bool vm2 = m2 < len;
            sc[m2 * LDSC + lane]      = (vm2 && (lane      < len)) ? e0 * inv : 0.f;
            sc[m2 * LDSC + lane + 32] = (vm2 && (lane + 32 < len)) ? e1 * inv : 0.f;
            sc[m2 * LDSC + lane + 64] = (vm2 && (lane + 64 < len)) ? e2 * inv : 0.f;
            sc[m2 * LDSC + lane + 96] = (vm2 && (lane + 96 < len)) ? e3 * inv : 0.f;
        }
    }
    __syncthreads();

    // self_attn = attn @ v ; fuse delta2_sum and write X
    {
        int d = tid & 63;
        for (int m3 = tid >> 6; m3 < MB; m3 += 4) {
            float acc = 0.f;
#pragma unroll 4
            for (int p = 0; p < MB; p++)
                acc += sc[m3 * LDSC + p] * v[p * LDJ + d];
            bool vm3 = m3 < len;
            int m1 = vm3 ? 1 : 0;
            int loc = traj[(n * MB + m3) * 3 + 1];
            float ds_sum = vm3 ? g_rowsum[loc - 1] : 0.f;
            float ve = vec[n * MB + m3];
            const float Lf = 8192.0f;
            float S_vsl = ds_sum;                 // SL = 0
            float S_vsu = 100.0f * Lf - ds_sum;
            float S_vtl = ve * Lf;                // TL = 0
            float S_vtu = (500.0f - ve) * Lf;
            float d2 = (emb_sl[m1 * DB + d] * S_vsu + emb_su[m1 * DB + d] * S_vsl) * 0.01f
                     + (emb_tl[m1 * DB + d] * S_vtu + emb_tu[m1 * DB + d] * S_vtl) * 0.002f;
            g_X[((size_t)n * MB + m3) * DB + d] = acc * d2;
        }
    }
}

// ---------------------------------------------------------------------------
// Kernel 3: out[r,l] = sum_d X[r,d]*W_out[l,d] + b_out[l]
// 128x128 output tile per CTA, 256 threads, 8x8 register microtile, K=64.
// ---------------------------------------------------------------------------
extern __shared__ float sm_gemm[];

__global__ __launch_bounds__(256) void out_gemm(
    const float* __restrict__ W_out,
    const float* __restrict__ b_out,
    float*       __restrict__ out)
{
    float* As = sm_gemm;              // [64][132]  (k-major X tile)
    float* Bs = As + 64 * 132;        // [64][132]  (k-major W tile)

    const int rB = blockIdx.y * 128;
    const int lB = blockIdx.x * 128;
    const int tid = threadIdx.x;

    // load + transpose X tile: As[k][m]
    {
        const float4* src = (const float4*)(g_X + (size_t)rB * 64);
        for (int t = tid; t < 128 * 16; t += 256) {
            float4 vv = src[t];
            int m = t >> 4, k0 = (t & 15) << 2;
            As[(k0 + 0) * 132 + m] = vv.x;
            As[(k0 + 1) * 132 + m] = vv.y;
            As[(k0 + 2) * 132 + m] = vv.z;
            As[(k0 + 3) * 132 + m] = vv.w;
        }
        const float4* srcB = (const float4*)(W_out + (size_t)lB * 64);
        for (int t = tid; t < 128 * 16; t += 256) {
            float4 vv = srcB[t];
            int j = t >> 4, k0 = (t & 15) << 2;
            Bs[(k0 + 0) * 132 + j] = vv.x;
            Bs[(k0 + 1) * 132 + j] = vv.y;
            Bs[(k0 + 2) * 132 + j] = vv.z;
            Bs[(k0 + 3) * 132 + j] = vv.w;
        }
    }
    __syncthreads();

    const int ty = tid >> 4, tx = tid & 15;
    float acc[8][8] = {};
#pragma unroll 8
    for (int k = 0; k < 64; k++) {
        float4 a0 = *(const float4*)&As[k * 132 + ty * 8];
        float4 a1 = *(const float4*)&As[k * 132 + ty * 8 + 4];
        float4 b0 = *(const float4*)&Bs[k * 132 + tx * 8];
        float4 b1 = *(const float4*)&Bs[k * 132 + tx * 8 + 4];
        float a[8] = {a0.x, a0.y, a0.z, a0.w, a1.x, a1.y, a1.z, a1.w};
        float b[8] = {b0.x, b0.y, b0.z, b0.w, b1.x, b1.y, b1.z, b1.w};
#pragma unroll
        for (int i = 0; i < 8; i++)
#pragma unroll
            for (int j = 0; j < 8; j++)
                acc[i][j] += a[i] * b[j];
    }

    float bb[8];
#pragma unroll
    for (int j = 0; j < 8; j++) bb[j] = b_out[lB + tx * 8 + j];

#pragma unroll
    for (int i = 0; i < 8; i++) {
        size_t off = (size_t)(rB + ty * 8 + i) * LB + lB + tx * 8;
        float4 o0 = {acc[i][0] + bb[0], acc[i][1] + bb[1], acc[i][2] + bb[2], acc[i][3] + bb[3]};
        float4 o1 = {acc[i][4] + bb[4], acc[i][5] + bb[5], acc[i][6] + bb[6], acc[i][7] + bb[7]};
        *(float4*)(out + off)     = o0;
        *(float4*)(out + off + 4) = o1;
    }
}

// ---------------------------------------------------------------------------
extern "C" void kernel_launch(void* const* d_in, const int* in_sizes, int n_in,
                              void* d_out, int out_size) {
    const int*   traj     = (const int*)  d_in[0];
    const float* mat1     = (const float*)d_in[1];
    const float* mat2s    = (const float*)d_in[2];
    const float* vec      = (const float*)d_in[3];
    const int*   traj_len = (const int*)  d_in[4];
    const float* emb_t    = (const float*)d_in[5];
    const float* emb_l    = (const float*)d_in[6];
    const float* emb_u    = (const float*)d_in[7];
    const float* emb_su   = (const float*)d_in[8];
    const float* emb_sl   = (const float*)d_in[9];
    const float* emb_tu   = (const float*)d_in[10];
    const float* emb_tl   = (const float*)d_in[11];
    const float* Wq       = (const float*)d_in[12];
    const float* Wk       = (const float*)d_in[13];
    const float* Wv       = (const float*)d_in[14];
    const float* W_out    = (const float*)d_in[15];
    const float* b_out    = (const float*)d_in[16];
    float* out = (float*)d_out;

    const int ATTN_SMEM = (4 * MB * LDJ + MB * LDSC + 8) * (int)sizeof(float); // 200,736 B
    const int GEMM_SMEM = 2 * 64 * 132 * (int)sizeof(float);                   // 67,584 B
    cudaFuncSetAttribute(attn_kernel, cudaFuncAttributeMaxDynamicSharedMemorySize, ATTN_SMEM);
    cudaFuncSetAttribute(out_gemm,   cudaFuncAttributeMaxDynamicSharedMemorySize, GEMM_SMEM);

    rowsum_kernel<<<LB, 256>>>(mat2s);
    attn_kernel<<<NB, 256, ATTN_SMEM>>>(traj, mat1, vec, traj_len,
                                        emb_t, emb_l, emb_u,
                                        emb_su, emb_sl, emb_tu, emb_tl,
                                        Wq, Wk, Wv);
    dim3 grid(LB / 128, (NB * MB) / 128);
    out_gemm<<<grid, 256, GEMM_SMEM>>>(W_out, b_out, out);
}

// round 3
// speedup vs baseline: 1.5498x; 1.5498x over previous
#include <cuda_runtime.h>
#include <cuda_bf16.h>
#include <cstdint>

#define NB 64
#define MB 128
#define LB 8192
#define DB 64
#define HOURS_C 168

#define LDJ 65
#define LDSC 132

// ---------------- scratch (no runtime allocation allowed) -------------------
__device__ float g_rowsum[LB];
__device__ __align__(16) __nv_bfloat16 g_Xhi[(size_t)NB * MB * DB];
__device__ __align__(16) __nv_bfloat16 g_Xlo[(size_t)NB * MB * DB];
__device__ __align__(16) __nv_bfloat16 g_Whi[(size_t)LB * DB];
__device__ __align__(16) __nv_bfloat16 g_Wlo[(size_t)LB * DB];

// ---------------- helpers ----------------------------------------------------
__device__ __forceinline__ uint32_t smem_u32(const void* p) {
    uint32_t a;
    asm("{ .reg .u64 t; cvta.to.shared.u64 t, %1; cvt.u32.u64 %0, t; }" : "=r"(a) : "l"(p));
    return a;
}
__device__ __forceinline__ void ldsm_x4(uint32_t* r, uint32_t addr) {
    asm volatile("ldmatrix.sync.aligned.m8n8.x4.shared.b16 {%0,%1,%2,%3}, [%4];"
                 : "=r"(r[0]), "=r"(r[1]), "=r"(r[2]), "=r"(r[3]) : "r"(addr));
}
__device__ __forceinline__ void mma16816(float* c, const uint32_t* a, uint32_t b0, uint32_t b1) {
    asm volatile(
        "mma.sync.aligned.m16n8k16.row.col.f32.bf16.bf16.f32 "
        "{%0,%1,%2,%3}, {%4,%5,%6,%7}, {%8,%9}, {%0,%1,%2,%3};"
        : "+f"(c[0]), "+f"(c[1]), "+f"(c[2]), "+f"(c[3])
        : "r"(a[0]), "r"(a[1]), "r"(a[2]), "r"(a[3]), "r"(b0), "r"(b1));
}

// ---------------------------------------------------------------------------
// Kernel 1: row sums of mat2s (L x L)
// ---------------------------------------------------------------------------
__global__ __launch_bounds__(256) void rowsum_kernel(const float* __restrict__ mat2s) {
    int l = blockIdx.x;
    const float4* row = (const float4*)(mat2s + (size_t)l * LB);
    float s = 0.f;
#pragma unroll
    for (int i = threadIdx.x; i < LB / 4; i += 256) {
        float4 v = row[i];
        s += v.x + v.y + v.z + v.w;
    }
    __shared__ float red[8];
#pragma unroll
    for (int o = 16; o; o >>= 1) s += __shfl_down_sync(~0u, s, o);
    if ((threadIdx.x & 31) == 0) red[threadIdx.x >> 5] = s;
    __syncthreads();
    if (threadIdx.x < 8) {
        s = red[threadIdx.x];
#pragma unroll
        for (int o = 4; o; o >>= 1) s += __shfl_down_sync(0xffu, s, o);
        if (threadIdx.x == 0) g_rowsum[l] = s;
    }
}

// ---------------------------------------------------------------------------
// Kernel 1b: split W_out into bf16 hi/lo
// ---------------------------------------------------------------------------
__global__ __launch_bounds__(256) void wsplit_kernel(const float* __restrict__ W) {
    int i = blockIdx.x * 256 + threadIdx.x;
    float x = W[i];
    __nv_bfloat16 h = __float2bfloat16(x);
    g_Whi[i] = h;
    g_Wlo[i] = __float2bfloat16(x - __bfloat162float(h));
}

// ---------------------------------------------------------------------------
// Kernel 2: per-batch attention -> X = self_attn * delta2 as bf16 hi/lo
// ---------------------------------------------------------------------------
extern __shared__ float sm_attn[];

__global__ __launch_bounds__(256) void attn_kernel(
    const int*   __restrict__ traj,
    const float* __restrict__ mat1,
    const float* __restrict__ vec,
    const int*   __restrict__ traj_len,
    const float* __restrict__ emb_t,
    const float* __restrict__ emb_l,
    const float* __restrict__ emb_u,
    const float* __restrict__ emb_su,
    const float* __restrict__ emb_sl,
    const float* __restrict__ emb_tu,
    const float* __restrict__ emb_tl,
    const float* __restrict__ Wq,
    const float* __restrict__ Wk,
    const float* __restrict__ Wv)
{
    const int n   = blockIdx.x;
    const int tid = threadIdx.x;

    float* joint = sm_attn;
    float* q     = joint + MB * LDJ;
    float* k     = q + MB * LDJ;
    float* v     = k + MB * LDJ;
    float* sc    = v + MB * LDJ;
    float* Ws    = sc;
    float* scal  = sc + MB * LDSC;

    const int len = traj_len[n];

    if (tid < 8) {
        int which = tid >> 1, row = tid & 1;
        const float* e = (which == 0) ? emb_sl : (which == 1) ? emb_su
                       : (which == 2) ? emb_tl : emb_tu;
        float s = 0.f;
#pragma unroll
        for (int d = 0; d < DB; d++) s += e[row * DB + d];
        scal[tid] = s;
    }

    for (int i = tid; i < MB * DB; i += 256) {
        int m = i >> 6, d = i & 63;
        int u   = traj[(n * MB + m) * 3 + 0];
        int loc = traj[(n * MB + m) * 3 + 1];
        int t   = traj[(n * MB + m) * 3 + 2];
        int ti  = (t - 1) % HOURS_C + 1;
        joint[m * LDJ + d] = emb_t[ti * DB + d] + emb_l[loc * DB + d] + emb_u[u * DB + d];
    }
    __syncthreads();

    const float* Wmats[3] = {Wq, Wk, Wv};
    float* outs[3] = {q, k, v};
#pragma unroll 1
    for (int w = 0; w < 3; w++) {
        for (int i = tid; i < DB * DB; i += 256)
            Ws[(i >> 6) * LDJ + (i & 63)] = Wmats[w][i];
        __syncthreads();
        for (int i = tid; i < MB * DB; i += 256) {
            int m = i >> 6, d = i & 63;
            float acc = 0.f;
#pragma unroll
            for (int j = 0; j < DB; j++)
                acc += joint[m * LDJ + j] * Ws[d * LDJ + j];
            outs[w][m * LDJ + d] = acc;
        }
        __syncthreads();
    }

    {
        int m = tid >> 1, half = tid & 1;
        bool vm = m < len;
        float qreg[DB];
#pragma unroll
        for (int j = 0; j < DB; j++) qreg[j] = q[m * LDJ + j];
        float s0 = scal[0], s1 = scal[1], s2 = scal[2], s3 = scal[3];
        float s4 = scal[4], s5 = scal[5], s6 = scal[6], s7 = scal[7];
#pragma unroll 2
        for (int pp = 0; pp < 64; pp++) {
            int p = half * 64 + pp;
            float acc = 0.f;
#pragma unroll
            for (int j = 0; j < DB; j++) acc += qreg[j] * k[p * LDJ + j];
            bool msk = vm && (p < len);
            float2 dd = ((const float2*)mat1)[(size_t)(n * MB + m) * MB + p];
            float ds = dd.x, dt = dd.y;
            float ssl = msk ? s1 : s0;
            float ssu = msk ? s3 : s2;
            float stl = msk ? s5 : s4;
            float stu = msk ? s7 : s6;
            float delta = (ssl * (100.0f - ds) + ssu * ds) * 0.01f
                        + (stl * (500.0f - dt) + stu * dt) * 0.002f;
            sc[m * LDSC + p] = acc + delta;
        }
    }
    __syncthreads();

    {
        int wid = tid >> 5, lane = tid & 31;
        for (int m2 = wid; m2 < MB; m2 += 8) {
            float v0 = sc[m2 * LDSC + lane];
            float v1 = sc[m2 * LDSC + lane + 32];
            float v2 = sc[m2 * LDSC + lane + 64];
            float v3 = sc[m2 * LDSC + lane + 96];
            float mx = fmaxf(fmaxf(v0, v1), fmaxf(v2, v3));
#pragma unroll
            for (int o = 16; o; o >>= 1) mx = fmaxf(mx, __shfl_xor_sync(~0u, mx, o));
            float e0 = __expf(v0 - mx), e1 = __expf(v1 - mx);
            float e2 = __expf(v2 - mx), e3 = __expf(v3 - mx);
            float sum = e0 + e1 + e2 + e3;
#pragma unroll
            for (int o = 16; o; o >>= 1) sum += __shfl_xor_sync(~0u, sum, o);
            float inv = 1.0f / sum;
            bool vm2 = m2 < len;
            sc[m2 * LDSC + lane]      = (vm2 && (lane      < len)) ? e0 * inv : 0.f;
            sc[m2 * LDSC + lane + 32] = (vm2 && (lane + 32 < len)) ? e1 * inv : 0.f;
            sc[m2 * LDSC + lane + 64] = (vm2 && (lane + 64 < len)) ? e2 * inv : 0.f;
            sc[m2 * LDSC + lane + 96] = (vm2 && (lane + 96 < len)) ? e3 * inv : 0.f;
        }
    }
    __syncthreads();

    {
        int d = tid & 63;
        for (int m3 = tid >> 6; m3 < MB; m3 += 4) {
            float acc = 0.f;
#pragma unroll 4
            for (int p = 0; p < MB; p++)
                acc += sc[m3 * LDSC + p] * v[p * LDJ + d];
            bool vm3 = m3 < len;
            int m1 = vm3 ? 1 : 0;
            int loc = traj[(n * MB + m3) * 3 + 1];
            float ds_sum = vm3 ? g_rowsum[loc - 1] : 0.f;
            float ve = vec[n * MB + m3];
            const float Lf = 8192.0f;
            float S_vsl = ds_sum;
            float S_vsu = 100.0f * Lf - ds_sum;
            float S_vtl = ve * Lf;
            float S_vtu = (500.0f - ve) * Lf;
            float d2 = (emb_sl[m1 * DB + d] * S_vsu + emb_su[m1 * DB + d] * S_vsl) * 0.01f
                     + (emb_tl[m1 * DB + d] * S_vtu + emb_tu[m1 * DB + d] * S_vtl) * 0.002f;
            float x = acc * d2;
            size_t idx = ((size_t)n * MB + m3) * DB + d;
            __nv_bfloat16 h = __float2bfloat16(x);
            g_Xhi[idx] = h;
            g_Xlo[idx] = __float2bfloat16(x - __bfloat162float(h));
        }
    }
}

// ---------------------------------------------------------------------------
// Kernel 3: split-bf16 GEMM via mma.sync (portable PTX -> HMMA on sm_103).
// out[r,l] = X[r,:]·W[l,:] + b[l].  CTA: 128x128 tile, 256 thr (8 warps 2x4).
// Warp: 64x32. 3 passes: hi·hi + hi·lo + lo·hi.
// ---------------------------------------------------------------------------
#define SA 72                          // padded bf16 row stride (144 B)
#define TILE_HB (128 * SA)             // bf16 elems per tile buffer

extern __shared__ __align__(16) __nv_bfloat16 sm_g[];

__global__ __launch_bounds__(256) void out_gemm_mma(
    const float* __restrict__ b_out, float* __restrict__ out)
{
    __nv_bfloat16* Ahi = sm_g;
    __nv_bfloat16* Alo = Ahi + TILE_HB;
    __nv_bfloat16* Bhi = Alo + TILE_HB;
    __nv_bfloat16* Blo = Bhi + TILE_HB;
    float* sbias = (float*)(Blo + TILE_HB);     // 128 floats

    const int tid  = threadIdx.x;
    const int wid  = tid >> 5;
    const int lane = tid & 31;
    const int wm   = wid & 1;          // 0..1 : 64-row strip
    const int wn   = wid >> 1;         // 0..3 : 32-col strip
    const int rB = blockIdx.y * 128;
    const int lB = blockIdx.x * 128;

    // ---- load tiles (128 rows x 64 bf16 = 8 uint4 per row) ----
    {
        const uint4* gA0 = (const uint4*)(g_Xhi + (size_t)rB * DB);
        const uint4* gA1 = (const uint4*)(g_Xlo + (size_t)rB * DB);
        const uint4* gB0 = (const uint4*)(g_Whi + (size_t)lB * DB);
        const uint4* gB1 = (const uint4*)(g_Wlo + (size_t)lB * DB);
#pragma unroll
        for (int it = 0; it < 4; it++) {
            int idx = it * 256 + tid;         // 1024 chunks
            int row = idx >> 3, ch = idx & 7;
            int so = row * SA + ch * 8;       // bf16 elems
            *(uint4*)(Ahi + so) = gA0[idx];
            *(uint4*)(Alo + so) = gA1[idx];
            *(uint4*)(Bhi + so) = gB0[idx];
            *(uint4*)(Blo + so) = gB1[idx];
        }
        if (tid < 128) sbias[tid] = b_out[lB + tid];
    }
    __syncthreads();

    const uint32_t sb = smem_u32(sm_g);
    const uint32_t aHi = sb;
    const uint32_t aLo = sb + TILE_HB * 2;
    const uint32_t bHi = sb + 2 * TILE_HB * 2;
    const uint32_t bLo = sb + 3 * TILE_HB * 2;

    // ldmatrix address pattern (same for A and B):
    // lanes 0-15: row = base_row + lane, col-elem 0; lanes 16-31: row + (lane-16), col-elem 8
    const int lrow = lane & 15;
    const int lcol = (lane >> 4) * 8;

    float acc[4][4][4];
#pragma unroll
    for (int i = 0; i < 4; i++)
#pragma unroll
        for (int j = 0; j < 4; j++)
#pragma unroll
            for (int c = 0; c < 4; c++) acc[i][j][c] = 0.f;

#pragma unroll
    for (int ks = 0; ks < 4; ks++) {
        const uint32_t koff = (uint32_t)(ks * 16 + lcol) * 2;
        uint32_t fAhi[4][4], fAlo[4][4];
#pragma unroll
        for (int mt = 0; mt < 4; mt++) {
            uint32_t ro = (uint32_t)((wm * 64 + mt * 16 + lrow) * SA) * 2 + koff;
            ldsm_x4(fAhi[mt], aHi + ro);
            ldsm_x4(fAlo[mt], aLo + ro);
        }
        uint32_t fBhi[2][4], fBlo[2][4];
#pragma unroll
        for (int nt2 = 0; nt2 < 2; nt2++) {
            uint32_t ro = (uint32_t)((wn * 32 + nt2 * 16 + lrow) * SA) * 2 + koff;
            ldsm_x4(fBhi[nt2], bHi + ro);
            ldsm_x4(fBlo[nt2], bLo + ro);
        }
#pragma unroll
        for (int mt = 0; mt < 4; mt++) {
#pragma unroll
            for (int nt = 0; nt < 4; nt++) {
                const int h = nt >> 1, o = nt & 1;   // ldsm x4: reg o = n-half, reg o+2 = k+8
                mma16816(acc[mt][nt], fAhi[mt], fBhi[h][o], fBhi[h][o + 2]);
                mma16816(acc[mt][nt], fAhi[mt], fBlo[h][o], fBlo[h][o + 2]);
                mma16816(acc[mt][nt], fAlo[mt], fBhi[h][o], fBhi[h][o + 2]);
            }
        }
    }

    // ---- epilogue: direct global stores (warp strip = 128B rows, L2 merges) ----
    const int gr = lane >> 2;             // 0..7
    const int gc = (lane & 3) * 2;        // 0,2,4,6
#pragma unroll
    for (int mt = 0; mt < 4; mt++) {
#pragma unroll
        for (int nt = 0; nt < 4; nt++) {
            int col = wn * 32 + nt * 8 + gc;
            float b0 = sbias[col], b1 = sbias[col + 1];
            size_t r0 = (size_t)(rB + wm * 64 + mt * 16 + gr) * LB + lB + col;
            float2 v0 = {acc[mt][nt][0] + b0, acc[mt][nt][1] + b1};
            float2 v1 = {acc[mt][nt][2] + b0, acc[mt][nt][3] + b1};
            *(float2*)(out + r0)            = v0;
            *(float2*)(out + r0 + 8 * LB)   = v1;
        }
    }
}

// ---------------------------------------------------------------------------
extern "C" void kernel_launch(void* const* d_in, const int* in_sizes, int n_in,
                              void* d_out, int out_size) {
    const int*   traj     = (const int*)  d_in[0];
    const float* mat1     = (const float*)d_in[1];
    const float* mat2s    = (const float*)d_in[2];
    const float* vec      = (const float*)d_in[3];
    const int*   traj_len = (const int*)  d_in[4];
    const float* emb_t    = (const float*)d_in[5];
    const float* emb_l    = (const float*)d_in[6];
    const float* emb_u    = (const float*)d_in[7];
    const float* emb_su   = (const float*)d_in[8];
    const float* emb_sl   = (const float*)d_in[9];
    const float* emb_tu   = (const float*)d_in[10];
    const float* emb_tl   = (const float*)d_in[11];
    const float* Wq       = (const float*)d_in[12];
    const float* Wk       = (const float*)d_in[13];
    const float* Wv       = (const float*)d_in[14];
    const float* W_out    = (const float*)d_in[15];
    const float* b_out    = (const float*)d_in[16];
    float* out = (float*)d_out;

    const int ATTN_SMEM = (4 * MB * LDJ + MB * LDSC + 8) * (int)sizeof(float);
    const int GEMM_SMEM = (4 * TILE_HB) * 2 + 128 * (int)sizeof(float);  // 74,240 B
    cudaFuncSetAttribute(attn_kernel,  cudaFuncAttributeMaxDynamicSharedMemorySize, ATTN_SMEM);
    cudaFuncSetAttribute(out_gemm_mma, cudaFuncAttributeMaxDynamicSharedMemorySize, GEMM_SMEM);

    rowsum_kernel<<<LB, 256>>>(mat2s);
    wsplit_kernel<<<(LB * DB) / 256, 256>>>(W_out);
    attn_kernel<<<NB, 256, ATTN_SMEM>>>(traj, mat1, vec, traj_len,
                                        emb_t, emb_l, emb_u,
                                        emb_su, emb_sl, emb_tu, emb_tl,
                                        Wq, Wk, Wv);
    dim3 grid(LB / 128, (NB * MB) / 128);
    out_gemm_mma<<<grid, 256, GEMM_SMEM>>>(b_out, out);
}

// round 4
// speedup vs baseline: 2.2075x; 1.4244x over previous
#include <cuda_runtime.h>
#include <cuda_bf16.h>
#include <cstdint>

#define NB 64
#define MB 128
#define LB 8192
#define DB 64
#define HOURS_C 168

// ---------------- scratch (no runtime allocation allowed) -------------------
__device__ float g_rowsum[LB];
__device__ __align__(16) float g_q[(size_t)NB * MB * DB];
__device__ __align__(16) float g_k[(size_t)NB * MB * DB];
__device__ __align__(16) float g_v[(size_t)NB * MB * DB];
__device__ __align__(16) __nv_bfloat16 g_Xhi[(size_t)NB * MB * DB];
__device__ __align__(16) __nv_bfloat16 g_Xlo[(size_t)NB * MB * DB];
__device__ __align__(16) __nv_bfloat16 g_Whi[(size_t)LB * DB];
__device__ __align__(16) __nv_bfloat16 g_Wlo[(size_t)LB * DB];

// ---------------- helpers ----------------------------------------------------
__device__ __forceinline__ uint32_t smem_u32(const void* p) {
    uint32_t a;
    asm("{ .reg .u64 t; cvta.to.shared.u64 t, %1; cvt.u32.u64 %0, t; }" : "=r"(a) : "l"(p));
    return a;
}
__device__ __forceinline__ void ldsm_x4(uint32_t* r, uint32_t addr) {
    asm volatile("ldmatrix.sync.aligned.m8n8.x4.shared.b16 {%0,%1,%2,%3}, [%4];"
                 : "=r"(r[0]), "=r"(r[1]), "=r"(r[2]), "=r"(r[3]) : "r"(addr));
}
__device__ __forceinline__ void mma16816(float* c, const uint32_t* a, uint32_t b0, uint32_t b1) {
    asm volatile(
        "mma.sync.aligned.m16n8k16.row.col.f32.bf16.bf16.f32 "
        "{%0,%1,%2,%3}, {%4,%5,%6,%7}, {%8,%9}, {%0,%1,%2,%3};"
        : "+f"(c[0]), "+f"(c[1]), "+f"(c[2]), "+f"(c[3])
        : "r"(a[0]), "r"(a[1]), "r"(a[2]), "r"(a[3]), "r"(b0), "r"(b1));
}

// ---------------------------------------------------------------------------
// Kernel 1: row sums of mat2s (L x L)
// ---------------------------------------------------------------------------
__global__ __launch_bounds__(256) void rowsum_kernel(const float* __restrict__ mat2s) {
    int l = blockIdx.x;
    const float4* row = (const float4*)(mat2s + (size_t)l * LB);
    float s = 0.f;
#pragma unroll
    for (int i = threadIdx.x; i < LB / 4; i += 256) {
        float4 v = row[i];
        s += v.x + v.y + v.z + v.w;
    }
    __shared__ float red[8];
#pragma unroll
    for (int o = 16; o; o >>= 1) s += __shfl_down_sync(~0u, s, o);
    if ((threadIdx.x & 31) == 0) red[threadIdx.x >> 5] = s;
    __syncthreads();
    if (threadIdx.x < 8) {
        s = red[threadIdx.x];
#pragma unroll
        for (int o = 4; o; o >>= 1) s += __shfl_down_sync(0xffu, s, o);
        if (threadIdx.x == 0) g_rowsum[l] = s;
    }
}

// ---------------------------------------------------------------------------
// Kernel 1b: split W_out into bf16 hi/lo
// ---------------------------------------------------------------------------
__global__ __launch_bounds__(256) void wsplit_kernel(const float* __restrict__ W) {
    int i = blockIdx.x * 256 + threadIdx.x;
    float x = W[i];
    __nv_bfloat16 h = __float2bfloat16(x);
    g_Whi[i] = h;
    g_Wlo[i] = __float2bfloat16(x - __bfloat162float(h));
}

// ---------------------------------------------------------------------------
// Kernel 2a: QKV. 128 CTAs x 64 rows. joint gather + 3 projections.
// ---------------------------------------------------------------------------
#define LJ 68   // float row stride for 64-wide tiles (16B-aligned, conflict-free)

__global__ __launch_bounds__(256) void qkv_kernel(
    const int*   __restrict__ traj,
    const float* __restrict__ emb_t,
    const float* __restrict__ emb_l,
    const float* __restrict__ emb_u,
    const float* __restrict__ Wq,
    const float* __restrict__ Wk,
    const float* __restrict__ Wv)
{
    __shared__ float joint[64 * LJ];
    __shared__ float Ws[64 * LJ];

    const int tid = threadIdx.x;
    const int r0  = blockIdx.x * 64;            // global row base

    // joint rows (gather)
    for (int i = tid; i < 64 * 64; i += 256) {
        int m = i >> 6, d = i & 63;
        int base = (r0 + m) * 3;
        int u   = traj[base + 0];
        int loc = traj[base + 1];
        int t   = traj[base + 2];
        int ti  = (t - 1) % HOURS_C + 1;
        joint[m * LJ + d] = emb_t[ti * DB + d] + emb_l[loc * DB + d] + emb_u[u * DB + d];
    }

    const int ty = tid >> 5;       // 0..7 -> 8-row strip
    const int tx = tid & 31;       // d0 = tx, d1 = tx + 32
    const float* Wmats[3] = {Wq, Wk, Wv};
    float* outs[3] = {g_q, g_k, g_v};

#pragma unroll 1
    for (int w = 0; w < 3; w++) {
        __syncthreads();
        for (int i = tid; i < 64 * 16; i += 256) {          // stage W (f4)
            int rr = i >> 4, c4 = i & 15;
            *(float4*)&Ws[rr * LJ + c4 * 4] = ((const float4*)Wmats[w])[i];
        }
        __syncthreads();

        float acc[8][2] = {};
#pragma unroll
        for (int j4 = 0; j4 < 16; j4++) {
            float4 b0 = *(const float4*)&Ws[tx * LJ + j4 * 4];
            float4 b1 = *(const float4*)&Ws[(tx + 32) * LJ + j4 * 4];
#pragma unroll
            for (int i = 0; i < 8; i++) {
                float4 a = *(const float4*)&joint[(ty * 8 + i) * LJ + j4 * 4];
                acc[i][0] += a.x * b0.x + a.y * b0.y + a.z * b0.z + a.w * b0.w;
                acc[i][1] += a.x * b1.x + a.y * b1.y + a.z * b1.z + a.w * b1.w;
            }
        }
        float* op = outs[w] + (size_t)(r0 + ty * 8) * DB;
#pragma unroll
        for (int i = 0; i < 8; i++) {
            op[i * DB + tx]      = acc[i][0];
            op[i * DB + tx + 32] = acc[i][1];
        }
    }
}

// ---------------------------------------------------------------------------
// Kernel 2b: scores + softmax + attn@v + delta2 -> X (bf16 hi/lo)
// grid (2, 64): blockIdx.y = n, blockIdx.x = m-half. 256 threads.
// ---------------------------------------------------------------------------
#define LSC 132

extern __shared__ float sm_s[];

__global__ __launch_bounds__(256) void scores_kernel(
    const int*   __restrict__ traj,
    const float* __restrict__ mat1,
    const float* __restrict__ vec,
    const int*   __restrict__ traj_len,
    const float* __restrict__ emb_su,
    const float* __restrict__ emb_sl,
    const float* __restrict__ emb_tu,
    const float* __restrict__ emb_tl)
{
    float* qs   = sm_s;                    // [64][LJ]
    float* ks   = qs + 64 * LJ;            // [128][LJ]
    float* vs   = ks + 128 * LJ;           // [128][LJ]
    float* sc   = vs + 128 * LJ;           // [64][LSC]
    float* scal = sc + 64 * LSC;           // 8

    const int n   = blockIdx.y;
    const int m0  = blockIdx.x * 64;       // global m base for this half
    const int tid = threadIdx.x;
    const int len = traj_len[n];

    if (tid < 8) {
        int which = tid >> 1, row = tid & 1;
        const float* e = (which == 0) ? emb_sl : (which == 1) ? emb_su
                       : (which == 2) ? emb_tl : emb_tu;
        float s = 0.f;
#pragma unroll
        for (int d = 0; d < DB; d++) s += e[row * DB + d];
        scal[tid] = s;
    }

    // load q (own half), k, v (full n)
    {
        const float4* gq = (const float4*)(g_q + (size_t)(n * MB + m0) * DB);
        for (int i = tid; i < 64 * 16; i += 256) {
            int rr = i >> 4, c4 = i & 15;
            *(float4*)&qs[rr * LJ + c4 * 4] = gq[i];
        }
        const float4* gk = (const float4*)(g_k + (size_t)n * MB * DB);
        const float4* gv = (const float4*)(g_v + (size_t)n * MB * DB);
        for (int i = tid; i < 128 * 16; i += 256) {
            int rr = i >> 4, c4 = i & 15;
            *(float4*)&ks[rr * LJ + c4 * 4] = gk[i];
            *(float4*)&vs[rr * LJ + c4 * 4] = gv[i];
        }
    }
    __syncthreads();

    const int ty = tid >> 5;      // 0..7 -> 8 m-rows
    const int tx = tid & 31;      // p = tx + 32*pp

    // ---- scores 64x128 ----
    {
        float acc[8][4] = {};
#pragma unroll
        for (int j4 = 0; j4 < 16; j4++) {
            float4 b[4];
#pragma unroll
            for (int pp = 0; pp < 4; pp++)
                b[pp] = *(const float4*)&ks[(tx + pp * 32) * LJ + j4 * 4];
#pragma unroll
            for (int i = 0; i < 8; i++) {
                float4 a = *(const float4*)&qs[(ty * 8 + i) * LJ + j4 * 4];
#pragma unroll
                for (int pp = 0; pp < 4; pp++)
                    acc[i][pp] += a.x * b[pp].x + a.y * b[pp].y + a.z * b[pp].z + a.w * b[pp].w;
            }
        }
        float s0 = scal[0], s1 = scal[1], s2 = scal[2], s3 = scal[3];
        float s4 = scal[4], s5 = scal[5], s6 = scal[6], s7 = scal[7];
#pragma unroll
        for (int i = 0; i < 8; i++) {
            int mg = m0 + ty * 8 + i;
            bool vm = mg < len;
            const float2* mrow = (const float2*)mat1 + (size_t)(n * MB + mg) * MB;
#pragma unroll
            for (int pp = 0; pp < 4; pp++) {
                int p = tx + pp * 32;
                bool msk = vm && (p < len);
                float2 dd = mrow[p];
                float ssl = msk ? s1 : s0;
                float ssu = msk ? s3 : s2;
                float stl = msk ? s5 : s4;
                float stu = msk ? s7 : s6;
                float delta = (ssl * (100.0f - dd.x) + ssu * dd.x) * 0.01f
                            + (stl * (500.0f - dd.y) + stu * dd.y) * 0.002f;
                sc[(ty * 8 + i) * LSC + p] = acc[i][pp] + delta;
            }
        }
    }
    __syncthreads();

    // ---- softmax (rows of 128) + ragged mask ----
    {
        int wid = tid >> 5, lane = tid & 31;
        for (int m2 = wid; m2 < 64; m2 += 8) {
            float v0 = sc[m2 * LSC + lane];
            float v1 = sc[m2 * LSC + lane + 32];
            float v2 = sc[m2 * LSC + lane + 64];
            float v3 = sc[m2 * LSC + lane + 96];
            float mx = fmaxf(fmaxf(v0, v1), fmaxf(v2, v3));
#pragma unroll
            for (int o = 16; o; o >>= 1) mx = fmaxf(mx, __shfl_xor_sync(~0u, mx, o));
            float e0 = __expf(v0 - mx), e1 = __expf(v1 - mx);
            float e2 = __expf(v2 - mx), e3 = __expf(v3 - mx);
            float sum = e0 + e1 + e2 + e3;
#pragma unroll
            for (int o = 16; o; o >>= 1) sum += __shfl_xor_sync(~0u, sum, o);
            float inv = 1.0f / sum;
            bool vm2 = (m0 + m2) < len;
            sc[m2 * LSC + lane]      = (vm2 && (lane      < len)) ? e0 * inv : 0.f;
            sc[m2 * LSC + lane + 32] = (vm2 && (lane + 32 < len)) ? e1 * inv : 0.f;
            sc[m2 * LSC + lane + 64] = (vm2 && (lane + 64 < len)) ? e2 * inv : 0.f;
            sc[m2 * LSC + lane + 96] = (vm2 && (lane + 96 < len)) ? e3 * inv : 0.f;
        }
    }
    __syncthreads();

    // ---- attn @ v (64x64) + delta2 + bf16 split store ----
    {
        float acc[8][2] = {};
#pragma unroll
        for (int p4 = 0; p4 < 32; p4++) {
            float b0[4], b1[4];
#pragma unroll
            for (int r = 0; r < 4; r++) {
                b0[r] = vs[(p4 * 4 + r) * LJ + tx];
                b1[r] = vs[(p4 * 4 + r) * LJ + tx + 32];
            }
#pragma unroll
            for (int i = 0; i < 8; i++) {
                float4 a = *(const float4*)&sc[(ty * 8 + i) * LSC + p4 * 4];
                acc[i][0] += a.x * b0[0] + a.y * b0[1] + a.z * b0[2] + a.w * b0[3];
                acc[i][1] += a.x * b1[0] + a.y * b1[1] + a.z * b1[2] + a.w * b1[3];
            }
        }
#pragma unroll
        for (int i = 0; i < 8; i++) {
            int mg = m0 + ty * 8 + i;
            bool vm = mg < len;
            int m1 = vm ? 1 : 0;
            int loc = traj[(n * MB + mg) * 3 + 1];
            float ds_sum = vm ? g_rowsum[loc - 1] : 0.f;
            float ve = vec[n * MB + mg];
            const float Lf = 8192.0f;
            float S_vsl = ds_sum;
            float S_vsu = 100.0f * Lf - ds_sum;
            float S_vtl = ve * Lf;
            float S_vtu = (500.0f - ve) * Lf;
            size_t base = (size_t)(n * MB + mg) * DB;
#pragma unroll
            for (int dd = 0; dd < 2; dd++) {
                int d = tx + dd * 32;
                float d2 = (emb_sl[m1 * DB + d] * S_vsu + emb_su[m1 * DB + d] * S_vsl) * 0.01f
                         + (emb_tl[m1 * DB + d] * S_vtu + emb_tu[m1 * DB + d] * S_vtl) * 0.002f;
                float x = acc[i][dd] * d2;
                __nv_bfloat16 h = __float2bfloat16(x);
                g_Xhi[base + d] = h;
                g_Xlo[base + d] = __float2bfloat16(x - __bfloat162float(h));
            }
        }
    }
}

// ---------------------------------------------------------------------------
// Kernel 3: split-bf16 GEMM via mma.sync. 128x128 tile/CTA, 8 warps (2x4).
// ---------------------------------------------------------------------------
#define SA 72
#define TILE_HB (128 * SA)

extern __shared__ __align__(16) __nv_bfloat16 sm_g[];

__global__ __launch_bounds__(256) void out_gemm_mma(
    const float* __restrict__ b_out, float* __restrict__ out)
{
    __nv_bfloat16* Ahi = sm_g;
    __nv_bfloat16* Alo = Ahi + TILE_HB;
    __nv_bfloat16* Bhi = Alo + TILE_HB;
    __nv_bfloat16* Blo = Bhi + TILE_HB;
    float* sbias = (float*)(Blo + TILE_HB);

    const int tid  = threadIdx.x;
    const int wid  = tid >> 5;
    const int lane = tid & 31;
    const int wm   = wid & 1;
    const int wn   = wid >> 1;
    const int rB = blockIdx.y * 128;
    const int lB = blockIdx.x * 128;

    {
        const uint4* gA0 = (const uint4*)(g_Xhi + (size_t)rB * DB);
        const uint4* gA1 = (const uint4*)(g_Xlo + (size_t)rB * DB);
        const uint4* gB0 = (const uint4*)(g_Whi + (size_t)lB * DB);
        const uint4* gB1 = (const uint4*)(g_Wlo + (size_t)lB * DB);
#pragma unroll
        for (int it = 0; it < 4; it++) {
            int idx = it * 256 + tid;
            int row = idx >> 3, ch = idx & 7;
            int so = row * SA + ch * 8;
            *(uint4*)(Ahi + so) = gA0[idx];
            *(uint4*)(Alo + so) = gA1[idx];
            *(uint4*)(Bhi + so) = gB0[idx];
            *(uint4*)(Blo + so) = gB1[idx];
        }
        if (tid < 128) sbias[tid] = b_out[lB + tid];
    }
    __syncthreads();

    const uint32_t sb = smem_u32(sm_g);
    const uint32_t aHi = sb;
    const uint32_t aLo = sb + TILE_HB * 2;
    const uint32_t bHi = sb + 2 * TILE_HB * 2;
    const uint32_t bLo = sb + 3 * TILE_HB * 2;

    const int lrow = lane & 15;
    const int lcol = (lane >> 4) * 8;

    float acc[4][4][4];
#pragma unroll
    for (int i = 0; i < 4; i++)
#pragma unroll
        for (int j = 0; j < 4; j++)
#pragma unroll
            for (int c = 0; c < 4; c++) acc[i][j][c] = 0.f;

#pragma unroll
    for (int ks = 0; ks < 4; ks++) {
        const uint32_t koff = (uint32_t)(ks * 16 + lcol) * 2;
        uint32_t fAhi[4][4], fAlo[4][4];
#pragma unroll
        for (int mt = 0; mt < 4; mt++) {
            uint32_t ro = (uint32_t)((wm * 64 + mt * 16 + lrow) * SA) * 2 + koff;
            ldsm_x4(fAhi[mt], aHi + ro);
            ldsm_x4(fAlo[mt], aLo + ro);
        }
        uint32_t fBhi[2][4], fBlo[2][4];
#pragma unroll
        for (int nt2 = 0; nt2 < 2; nt2++) {
            uint32_t ro = (uint32_t)((wn * 32 + nt2 * 16 + lrow) * SA) * 2 + koff;
            ldsm_x4(fBhi[nt2], bHi + ro);
            ldsm_x4(fBlo[nt2], bLo + ro);
        }
        // pass-major: same-acc MMAs spaced 16 apart
#pragma unroll
        for (int mt = 0; mt < 4; mt++)
#pragma unroll
            for (int nt = 0; nt < 4; nt++) {
                const int h = nt >> 1, o = nt & 1;
                mma16816(acc[mt][nt], fAhi[mt], fBhi[h][o], fBhi[h][o + 2]);
            }
#pragma unroll
        for (int mt = 0; mt < 4; mt++)
#pragma unroll
            for (int nt = 0; nt < 4; nt++) {
                const int h = nt >> 1, o = nt & 1;
                mma16816(acc[mt][nt], fAhi[mt], fBlo[h][o], fBlo[h][o + 2]);
            }
#pragma unroll
        for (int mt = 0; mt < 4; mt++)
#pragma unroll
            for (int nt = 0; nt < 4; nt++) {
                const int h = nt >> 1, o = nt & 1;
                mma16816(acc[mt][nt], fAlo[mt], fBhi[h][o], fBhi[h][o + 2]);
            }
    }

    const int gr = lane >> 2;
    const int gc = (lane & 3) * 2;
#pragma unroll
    for (int mt = 0; mt < 4; mt++) {
#pragma unroll
        for (int nt = 0; nt < 4; nt++) {
            int col = wn * 32 + nt * 8 + gc;
            float b0 = sbias[col], b1 = sbias[col + 1];
            size_t r0 = (size_t)(rB + wm * 64 + mt * 16 + gr) * LB + lB + col;
            float2 v0 = {acc[mt][nt][0] + b0, acc[mt][nt][1] + b1};
            float2 v1 = {acc[mt][nt][2] + b0, acc[mt][nt][3] + b1};
            *(float2*)(out + r0)          = v0;
            *(float2*)(out + r0 + 8 * LB) = v1;
        }
    }
}

// ---------------------------------------------------------------------------
extern "C" void kernel_launch(void* const* d_in, const int* in_sizes, int n_in,
                              void* d_out, int out_size) {
    const int*   traj     = (const int*)  d_in[0];
    const float* mat1     = (const float*)d_in[1];
    const float* mat2s    = (const float*)d_in[2];
    const float* vec      = (const float*)d_in[3];
    const int*   traj_len = (const int*)  d_in[4];
    const float* emb_t    = (const float*)d_in[5];
    const float* emb_l    = (const float*)d_in[6];
    const float* emb_u    = (const float*)d_in[7];
    const float* emb_su   = (const float*)d_in[8];
    const float* emb_sl   = (const float*)d_in[9];
    const float* emb_tu   = (const float*)d_in[10];
    const float* emb_tl   = (const float*)d_in[11];
    const float* Wq       = (const float*)d_in[12];
    const float* Wk       = (const float*)d_in[13];
    const float* Wv       = (const float*)d_in[14];
    const float* W_out    = (const float*)d_in[15];
    const float* b_out    = (const float*)d_in[16];
    float* out = (float*)d_out;

    const int SC_SMEM = (64 * LJ + 128 * LJ + 128 * LJ + 64 * LSC + 8) * (int)sizeof(float);
    const int GEMM_SMEM = (4 * TILE_HB) * 2 + 128 * (int)sizeof(float);
    cudaFuncSetAttribute(scores_kernel, cudaFuncAttributeMaxDynamicSharedMemorySize, SC_SMEM);
    cudaFuncSetAttribute(out_gemm_mma,  cudaFuncAttributeMaxDynamicSharedMemorySize, GEMM_SMEM);

    rowsum_kernel<<<LB, 256>>>(mat2s);
    wsplit_kernel<<<(LB * DB) / 256, 256>>>(W_out);
    qkv_kernel<<<(NB * MB) / 64, 256>>>(traj, emb_t, emb_l, emb_u, Wq, Wk, Wv);
    dim3 sg(2, NB);
    scores_kernel<<<sg, 256, SC_SMEM>>>(traj, mat1, vec, traj_len,
                                        emb_su, emb_sl, emb_tu, emb_tl);
    dim3 grid(LB / 128, (NB * MB) / 128);
    out_gemm_mma<<<grid, 256, GEMM_SMEM>>>(b_out, out);
}

// round 5
// speedup vs baseline: 2.6856x; 1.2166x over previous
#include <cuda_runtime.h>
#include <cuda_fp16.h>
#include <cstdint>

#define NB 64
#define MB 128
#define LB 8192
#define DB 64
#define HOURS_C 168

// ---------------- scratch (no runtime allocation allowed) -------------------
__device__ float g_rowsum[LB];
__device__ __align__(16) float g_q[(size_t)NB * MB * DB];
__device__ __align__(16) float g_k[(size_t)NB * MB * DB];
__device__ __align__(16) float g_v[(size_t)NB * MB * DB];
__device__ __align__(16) __half g_Xhi[(size_t)NB * MB * DB];
__device__ __align__(16) __half g_Xlo[(size_t)NB * MB * DB];
__device__ __align__(16) __half g_Wh[(size_t)LB * DB];

// ---------------- helpers ----------------------------------------------------
__device__ __forceinline__ uint32_t smem_u32(const void* p) {
    uint32_t a;
    asm("{ .reg .u64 t; cvta.to.shared.u64 t, %1; cvt.u32.u64 %0, t; }" : "=r"(a) : "l"(p));
    return a;
}
__device__ __forceinline__ void ldsm_x4(uint32_t* r, uint32_t addr) {
    asm volatile("ldmatrix.sync.aligned.m8n8.x4.shared.b16 {%0,%1,%2,%3}, [%4];"
                 : "=r"(r[0]), "=r"(r[1]), "=r"(r[2]), "=r"(r[3]) : "r"(addr));
}
__device__ __forceinline__ void mma16816(float* c, const uint32_t* a, uint32_t b0, uint32_t b1) {
    asm volatile(
        "mma.sync.aligned.m16n8k16.row.col.f32.f16.f16.f32 "
        "{%0,%1,%2,%3}, {%4,%5,%6,%7}, {%8,%9}, {%0,%1,%2,%3};"
        : "+f"(c[0]), "+f"(c[1]), "+f"(c[2]), "+f"(c[3])
        : "r"(a[0]), "r"(a[1]), "r"(a[2]), "r"(a[3]), "r"(b0), "r"(b1));
}

// ---------------------------------------------------------------------------
// Kernel 1: row sums of mat2s (L x L)
// ---------------------------------------------------------------------------
__global__ __launch_bounds__(256) void rowsum_kernel(const float* __restrict__ mat2s) {
    int l = blockIdx.x;
    const float4* row = (const float4*)(mat2s + (size_t)l * LB);
    float s = 0.f;
#pragma unroll
    for (int i = threadIdx.x; i < LB / 4; i += 256) {
        float4 v = row[i];
        s += v.x + v.y + v.z + v.w;
    }
    __shared__ float red[8];
#pragma unroll
    for (int o = 16; o; o >>= 1) s += __shfl_down_sync(~0u, s, o);
    if ((threadIdx.x & 31) == 0) red[threadIdx.x >> 5] = s;
    __syncthreads();
    if (threadIdx.x < 8) {
        s = red[threadIdx.x];
#pragma unroll
        for (int o = 4; o; o >>= 1) s += __shfl_down_sync(0xffu, s, o);
        if (threadIdx.x == 0) g_rowsum[l] = s;
    }
}

// ---------------------------------------------------------------------------
// Kernel 1b: W_out -> fp16
// ---------------------------------------------------------------------------
__global__ __launch_bounds__(256) void wsplit_kernel(const float* __restrict__ W) {
    int i = blockIdx.x * 256 + threadIdx.x;
    g_Wh[i] = __float2half(W[i]);
}

// ---------------------------------------------------------------------------
// Kernel 2a: QKV. 256 CTAs x 32 rows.
// ---------------------------------------------------------------------------
#define LJ 68

__global__ __launch_bounds__(256) void qkv_kernel(
    const int*   __restrict__ traj,
    const float* __restrict__ emb_t,
    const float* __restrict__ emb_l,
    const float* __restrict__ emb_u,
    const float* __restrict__ Wq,
    const float* __restrict__ Wk,
    const float* __restrict__ Wv)
{
    __shared__ float joint[32 * LJ];
    __shared__ float Ws[64 * LJ];

    const int tid = threadIdx.x;
    const int r0  = blockIdx.x * 32;

    for (int i = tid; i < 32 * 64; i += 256) {
        int m = i >> 6, d = i & 63;
        int base = (r0 + m) * 3;
        int u   = traj[base + 0];
        int loc = traj[base + 1];
        int t   = traj[base + 2];
        int ti  = (t - 1) % HOURS_C + 1;
        joint[m * LJ + d] = emb_t[ti * DB + d] + emb_l[loc * DB + d] + emb_u[u * DB + d];
    }

    const int ty = tid >> 5;
    const int tx = tid & 31;
    const float* Wmats[3] = {Wq, Wk, Wv};
    float* outs[3] = {g_q, g_k, g_v};

#pragma unroll 1
    for (int w = 0; w < 3; w++) {
        __syncthreads();
        for (int i = tid; i < 64 * 16; i += 256) {
            int rr = i >> 4, c4 = i & 15;
            *(float4*)&Ws[rr * LJ + c4 * 4] = ((const float4*)Wmats[w])[i];
        }
        __syncthreads();

        float acc[4][2] = {};
#pragma unroll
        for (int j4 = 0; j4 < 16; j4++) {
            float4 b0 = *(const float4*)&Ws[tx * LJ + j4 * 4];
            float4 b1 = *(const float4*)&Ws[(tx + 32) * LJ + j4 * 4];
#pragma unroll
            for (int i = 0; i < 4; i++) {
                float4 a = *(const float4*)&joint[(ty * 4 + i) * LJ + j4 * 4];
                acc[i][0] += a.x * b0.x + a.y * b0.y + a.z * b0.z + a.w * b0.w;
                acc[i][1] += a.x * b1.x + a.y * b1.y + a.z * b1.z + a.w * b1.w;
            }
        }
        float* op = outs[w] + (size_t)(r0 + ty * 4) * DB;
#pragma unroll
        for (int i = 0; i < 4; i++) {
            op[i * DB + tx]      = acc[i][0];
            op[i * DB + tx + 32] = acc[i][1];
        }
    }
}

// ---------------------------------------------------------------------------
// Kernel 2b: scores + softmax + attn@v + delta2 -> X (fp16 hi/lo)
// grid (4, 64): blockIdx.y = n, blockIdx.x = 32-row m-tile. 256 threads.
// ---------------------------------------------------------------------------
#define LSC 132

extern __shared__ float sm_s[];

__global__ __launch_bounds__(256) void scores_kernel(
    const int*   __restrict__ traj,
    const float* __restrict__ mat1,
    const float* __restrict__ vec,
    const int*   __restrict__ traj_len,
    const float* __restrict__ emb_su,
    const float* __restrict__ emb_sl,
    const float* __restrict__ emb_tu,
    const float* __restrict__ emb_tl)
{
    float* qs   = sm_s;                    // [32][LJ]
    float* ks   = qs + 32 * LJ;            // [128][LJ]
    float* vs   = ks + 128 * LJ;           // [128][LJ]
    float* sc   = vs + 128 * LJ;           // [32][LSC]
    float* scal = sc + 32 * LSC;           // 8

    const int n   = blockIdx.y;
    const int m0  = blockIdx.x * 32;
    const int tid = threadIdx.x;
    const int len = traj_len[n];

    if (tid < 8) {
        int which = tid >> 1, row = tid & 1;
        const float* e = (which == 0) ? emb_sl : (which == 1) ? emb_su
                       : (which == 2) ? emb_tl : emb_tu;
        float s = 0.f;
#pragma unroll
        for (int d = 0; d < DB; d++) s += e[row * DB + d];
        scal[tid] = s;
    }

    {
        const float4* gq = (const float4*)(g_q + (size_t)(n * MB + m0) * DB);
        for (int i = tid; i < 32 * 16; i += 256) {
            int rr = i >> 4, c4 = i & 15;
            *(float4*)&qs[rr * LJ + c4 * 4] = gq[i];
        }
        const float4* gk = (const float4*)(g_k + (size_t)n * MB * DB);
        const float4* gv = (const float4*)(g_v + (size_t)n * MB * DB);
        for (int i = tid; i < 128 * 16; i += 256) {
            int rr = i >> 4, c4 = i & 15;
            *(float4*)&ks[rr * LJ + c4 * 4] = gk[i];
            *(float4*)&vs[rr * LJ + c4 * 4] = gv[i];
        }
    }
    __syncthreads();

    const int ty = tid >> 5;      // 4 m-rows each
    const int tx = tid & 31;

    // ---- scores 32x128 ----
    {
        float acc[4][4] = {};
#pragma unroll
        for (int j4 = 0; j4 < 16; j4++) {
            float4 b[4];
#pragma unroll
            for (int pp = 0; pp < 4; pp++)
                b[pp] = *(const float4*)&ks[(tx + pp * 32) * LJ + j4 * 4];
#pragma unroll
            for (int i = 0; i < 4; i++) {
                float4 a = *(const float4*)&qs[(ty * 4 + i) * LJ + j4 * 4];
#pragma unroll
                for (int pp = 0; pp < 4; pp++)
                    acc[i][pp] += a.x * b[pp].x + a.y * b[pp].y + a.z * b[pp].z + a.w * b[pp].w;
            }
        }
        float s0 = scal[0], s1 = scal[1], s2 = scal[2], s3 = scal[3];
        float s4 = scal[4], s5 = scal[5], s6 = scal[6], s7 = scal[7];
#pragma unroll
        for (int i = 0; i < 4; i++) {
            int mg = m0 + ty * 4 + i;
            bool vm = mg < len;
            const float2* mrow = (const float2*)mat1 + (size_t)(n * MB + mg) * MB;
#pragma unroll
            for (int pp = 0; pp < 4; pp++) {
                int p = tx + pp * 32;
                bool msk = vm && (p < len);
                float2 dd = mrow[p];
                float ssl = msk ? s1 : s0;
                float ssu = msk ? s3 : s2;
                float stl = msk ? s5 : s4;
                float stu = msk ? s7 : s6;
                float delta = (ssl * (100.0f - dd.x) + ssu * dd.x) * 0.01f
                            + (stl * (500.0f - dd.y) + stu * dd.y) * 0.002f;
                sc[(ty * 4 + i) * LSC + p] = acc[i][pp] + delta;
            }
        }
    }
    __syncthreads();

    // ---- softmax + ragged mask ----
    {
        int wid = tid >> 5, lane = tid & 31;
        for (int m2 = wid; m2 < 32; m2 += 8) {
            float v0 = sc[m2 * LSC + lane];
            float v1 = sc[m2 * LSC + lane + 32];
            float v2 = sc[m2 * LSC + lane + 64];
            float v3 = sc[m2 * LSC + lane + 96];
            float mx = fmaxf(fmaxf(v0, v1), fmaxf(v2, v3));
#pragma unroll
            for (int o = 16; o; o >>= 1) mx = fmaxf(mx, __shfl_xor_sync(~0u, mx, o));
            float e0 = __expf(v0 - mx), e1 = __expf(v1 - mx);
            float e2 = __expf(v2 - mx), e3 = __expf(v3 - mx);
            float sum = e0 + e1 + e2 + e3;
#pragma unroll
            for (int o = 16; o; o >>= 1) sum += __shfl_xor_sync(~0u, sum, o);
            float inv = 1.0f / sum;
            bool vm2 = (m0 + m2) < len;
            sc[m2 * LSC + lane]      = (vm2 && (lane      < len)) ? e0 * inv : 0.f;
            sc[m2 * LSC + lane + 32] = (vm2 && (lane + 32 < len)) ? e1 * inv : 0.f;
            sc[m2 * LSC + lane + 64] = (vm2 && (lane + 64 < len)) ? e2 * inv : 0.f;
            sc[m2 * LSC + lane + 96] = (vm2 && (lane + 96 < len)) ? e3 * inv : 0.f;
        }
    }
    __syncthreads();

    // ---- attn @ v (32x64) + delta2 + fp16 split store ----
    {
        float acc[4][2] = {};
#pragma unroll
        for (int p4 = 0; p4 < 32; p4++) {
            float b0[4], b1[4];
#pragma unroll
            for (int r = 0; r < 4; r++) {
                b0[r] = vs[(p4 * 4 + r) * LJ + tx];
                b1[r] = vs[(p4 * 4 + r) * LJ + tx + 32];
            }
#pragma unroll
            for (int i = 0; i < 4; i++) {
                float4 a = *(const float4*)&sc[(ty * 4 + i) * LSC + p4 * 4];
                acc[i][0] += a.x * b0[0] + a.y * b0[1] + a.z * b0[2] + a.w * b0[3];
                acc[i][1] += a.x * b1[0] + a.y * b1[1] + a.z * b1[2] + a.w * b1[3];
            }
        }
#pragma unroll
        for (int i = 0; i < 4; i++) {
            int mg = m0 + ty * 4 + i;
            bool vm = mg < len;
            int m1 = vm ? 1 : 0;
            int loc = traj[(n * MB + mg) * 3 + 1];
            float ds_sum = vm ? g_rowsum[loc - 1] : 0.f;
            float ve = vec[n * MB + mg];
            const float Lf = 8192.0f;
            float S_vsl = ds_sum;
            float S_vsu = 100.0f * Lf - ds_sum;
            float S_vtl = ve * Lf;
            float S_vtu = (500.0f - ve) * Lf;
            size_t base = (size_t)(n * MB + mg) * DB;
#pragma unroll
            for (int dd = 0; dd < 2; dd++) {
                int d = tx + dd * 32;
                float d2 = (emb_sl[m1 * DB + d] * S_vsu + emb_su[m1 * DB + d] * S_vsl) * 0.01f
                         + (emb_tl[m1 * DB + d] * S_vtu + emb_tu[m1 * DB + d] * S_vtl) * 0.002f;
                float x = acc[i][dd] * d2;
                __half h = __float2half(x);
                g_Xhi[base + d] = h;
                g_Xlo[base + d] = __float2half(x - __half2float(h));
            }
        }
    }
}

// ---------------------------------------------------------------------------
// Kernel 3: split-fp16 GEMM via mma.sync. 128x128 tile/CTA, 8 warps (2x4).
// 2 passes: Xhi·Wh + Xlo·Wh  (dropped X·(W - fp16(W)) ~ 1.4e-4 rel)
// ---------------------------------------------------------------------------
#define SA 72
#define TILE_HB (128 * SA)

extern __shared__ __align__(16) __half sm_g[];

__global__ __launch_bounds__(256) void out_gemm_mma(
    const float* __restrict__ b_out, float* __restrict__ out)
{
    __half* Ahi = sm_g;
    __half* Alo = Ahi + TILE_HB;
    __half* Bh  = Alo + TILE_HB;
    float* sbias = (float*)(Bh + TILE_HB);

    const int tid  = threadIdx.x;
    const int wid  = tid >> 5;
    const int lane = tid & 31;
    const int wm   = wid & 1;
    const int wn   = wid >> 1;
    const int rB = blockIdx.y * 128;
    const int lB = blockIdx.x * 128;

    {
        const uint4* gA0 = (const uint4*)(g_Xhi + (size_t)rB * DB);
        const uint4* gA1 = (const uint4*)(g_Xlo + (size_t)rB * DB);
        const uint4* gB0 = (const uint4*)(g_Wh + (size_t)lB * DB);
#pragma unroll
        for (int it = 0; it < 4; it++) {
            int idx = it * 256 + tid;
            int row = idx >> 3, ch = idx & 7;
            int so = row * SA + ch * 8;
            *(uint4*)(Ahi + so) = gA0[idx];
            *(uint4*)(Alo + so) = gA1[idx];
            *(uint4*)(Bh + so)  = gB0[idx];
        }
        if (tid < 128) sbias[tid] = b_out[lB + tid];
    }
    __syncthreads();

    const uint32_t sb = smem_u32(sm_g);
    const uint32_t aHi = sb;
    const uint32_t aLo = sb + TILE_HB * 2;
    const uint32_t bH  = sb + 2 * TILE_HB * 2;

    const int lrow = lane & 15;
    const int lcol = (lane >> 4) * 8;

    float acc[4][4][4];
#pragma unroll
    for (int i = 0; i < 4; i++)
#pragma unroll
        for (int j = 0; j < 4; j++)
#pragma unroll
            for (int c = 0; c < 4; c++) acc[i][j][c] = 0.f;

#pragma unroll
    for (int ks = 0; ks < 4; ks++) {
        const uint32_t koff = (uint32_t)(ks * 16 + lcol) * 2;
        uint32_t fAhi[4][4], fAlo[4][4];
#pragma unroll
        for (int mt = 0; mt < 4; mt++) {
            uint32_t ro = (uint32_t)((wm * 64 + mt * 16 + lrow) * SA) * 2 + koff;
            ldsm_x4(fAhi[mt], aHi + ro);
            ldsm_x4(fAlo[mt], aLo + ro);
        }
        uint32_t fB[2][4];
#pragma unroll
        for (int nt2 = 0; nt2 < 2; nt2++) {
            uint32_t ro = (uint32_t)((wn * 32 + nt2 * 16 + lrow) * SA) * 2 + koff;
            ldsm_x4(fB[nt2], bH + ro);
        }
#pragma unroll
        for (int mt = 0; mt < 4; mt++)
#pragma unroll
            for (int nt = 0; nt < 4; nt++) {
                const int h = nt >> 1, o = nt & 1;
                mma16816(acc[mt][nt], fAhi[mt], fB[h][o], fB[h][o + 2]);
            }
#pragma unroll
        for (int mt = 0; mt < 4; mt++)
#pragma unroll
            for (int nt = 0; nt < 4; nt++) {
                const int h = nt >> 1, o = nt & 1;
                mma16816(acc[mt][nt], fAlo[mt], fB[h][o], fB[h][o + 2]);
            }
    }

    const int gr = lane >> 2;
    const int gc = (lane & 3) * 2;
#pragma unroll
    for (int mt = 0; mt < 4; mt++) {
#pragma unroll
        for (int nt = 0; nt < 4; nt++) {
            int col = wn * 32 + nt * 8 + gc;
            float b0 = sbias[col], b1 = sbias[col + 1];
            size_t r0 = (size_t)(rB + wm * 64 + mt * 16 + gr) * LB + lB + col;
            float2 v0 = {acc[mt][nt][0] + b0, acc[mt][nt][1] + b1};
            float2 v1 = {acc[mt][nt][2] + b0, acc[mt][nt][3] + b1};
            *(float2*)(out + r0)          = v0;
            *(float2*)(out + r0 + 8 * LB) = v1;
        }
    }
}

// ---------------------------------------------------------------------------
extern "C" void kernel_launch(void* const* d_in, const int* in_sizes, int n_in,
                              void* d_out, int out_size) {
    const int*   traj     = (const int*)  d_in[0];
    const float* mat1     = (const float*)d_in[1];
    const float* mat2s    = (const float*)d_in[2];
    const float* vec      = (const float*)d_in[3];
    const int*   traj_len = (const int*)  d_in[4];
    const float* emb_t    = (const float*)d_in[5];
    const float* emb_l    = (const float*)d_in[6];
    const float* emb_u    = (const float*)d_in[7];
    const float* emb_su   = (const float*)d_in[8];
    const float* emb_sl   = (const float*)d_in[9];
    const float* emb_tu   = (const float*)d_in[10];
    const float* emb_tl   = (const float*)d_in[11];
    const float* Wq       = (const float*)d_in[12];
    const float* Wk       = (const float*)d_in[13];
    const float* Wv       = (const float*)d_in[14];
    const float* W_out    = (const float*)d_in[15];
    const float* b_out    = (const float*)d_in[16];
    float* out = (float*)d_out;

    const int SC_SMEM = (32 * LJ + 128 * LJ + 128 * LJ + 32 * LSC + 8) * (int)sizeof(float);
    const int GEMM_SMEM = (3 * TILE_HB) * 2 + 128 * (int)sizeof(float);
    cudaFuncSetAttribute(scores_kernel, cudaFuncAttributeMaxDynamicSharedMemorySize, SC_SMEM);
    cudaFuncSetAttribute(out_gemm_mma,  cudaFuncAttributeMaxDynamicSharedMemorySize, GEMM_SMEM);

    rowsum_kernel<<<LB, 256>>>(mat2s);
    wsplit_kernel<<<(LB * DB) / 256, 256>>>(W_out);
    qkv_kernel<<<(NB * MB) / 32, 256>>>(traj, emb_t, emb_l, emb_u, Wq, Wk, Wv);
    dim3 sg(4, NB);
    scores_kernel<<<sg, 256, SC_SMEM>>>(traj, mat1, vec, traj_len,
                                        emb_su, emb_sl, emb_tu, emb_tl);
    dim3 grid(LB / 128, (NB * MB) / 128);
    out_gemm_mma<<<grid, 256, GEMM_SMEM>>>(b_out, out);
}

// round 6
// speedup vs baseline: 3.0829x; 1.1479x over previous
#include <cuda_runtime.h>
#include <cuda_fp16.h>
#include <cstdint>

#define NB 64
#define MB 128
#define LB 8192
#define DB 64
#define HOURS_C 168

// ---------------- scratch (no runtime allocation allowed) -------------------
__device__ float g_rowsum[LB];
__device__ unsigned char g_need[LB];
__device__ __align__(16) float g_q[(size_t)NB * MB * DB];
__device__ __align__(16) float g_k[(size_t)NB * MB * DB];
__device__ __align__(16) float g_v[(size_t)NB * MB * DB];
__device__ __align__(16) __half g_Xh[(size_t)NB * MB * DB];
__device__ __align__(16) __half g_Wh[(size_t)LB * DB];

// ---------------- helpers ----------------------------------------------------
__device__ __forceinline__ uint32_t smem_u32(const void* p) {
    uint32_t a;
    asm("{ .reg .u64 t; cvta.to.shared.u64 t, %1; cvt.u32.u64 %0, t; }" : "=r"(a) : "l"(p));
    return a;
}
__device__ __forceinline__ void ldsm_x4(uint32_t* r, uint32_t addr) {
    asm volatile("ldmatrix.sync.aligned.m8n8.x4.shared.b16 {%0,%1,%2,%3}, [%4];"
                 : "=r"(r[0]), "=r"(r[1]), "=r"(r[2]), "=r"(r[3]) : "r"(addr));
}
__device__ __forceinline__ void mma16816(float* c, const uint32_t* a, uint32_t b0, uint32_t b1) {
    asm volatile(
        "mma.sync.aligned.m16n8k16.row.col.f32.f16.f16.f32 "
        "{%0,%1,%2,%3}, {%4,%5,%6,%7}, {%8,%9}, {%0,%1,%2,%3};"
        : "+f"(c[0]), "+f"(c[1]), "+f"(c[2]), "+f"(c[3])
        : "r"(a[0]), "r"(a[1]), "r"(a[2]), "r"(a[3]), "r"(b0), "r"(b1));
}

// ---------------------------------------------------------------------------
// Kernel 0: zero need-flags (graph-replay safe: re-zeroed every launch)
// ---------------------------------------------------------------------------
__global__ __launch_bounds__(256) void zero_flags_kernel() {
    ((uint4*)g_need)[blockIdx.x * 256 + threadIdx.x] = uint4{0, 0, 0, 0};
}

// ---------------------------------------------------------------------------
// Kernel 1: conditional row sums of mat2s — only rows marked needed
// ---------------------------------------------------------------------------
__global__ __launch_bounds__(256) void rowsum_kernel(const float* __restrict__ mat2s) {
    int l = blockIdx.x;
    if (!g_need[l]) return;
    const float4* row = (const float4*)(mat2s + (size_t)l * LB);
    float s = 0.f;
#pragma unroll
    for (int i = threadIdx.x; i < LB / 4; i += 256) {
        float4 v = row[i];
        s += v.x + v.y + v.z + v.w;
    }
    __shared__ float red[8];
#pragma unroll
    for (int o = 16; o; o >>= 1) s += __shfl_down_sync(~0u, s, o);
    if ((threadIdx.x & 31) == 0) red[threadIdx.x >> 5] = s;
    __syncthreads();
    if (threadIdx.x < 8) {
        s = red[threadIdx.x];
#pragma unroll
        for (int o = 4; o; o >>= 1) s += __shfl_down_sync(0xffu, s, o);
        if (threadIdx.x == 0) g_rowsum[l] = s;
    }
}

// ---------------------------------------------------------------------------
// Kernel 1b: W_out -> fp16
// ---------------------------------------------------------------------------
__global__ __launch_bounds__(256) void wsplit_kernel(const float* __restrict__ W) {
    int i = blockIdx.x * 256 + threadIdx.x;
    g_Wh[i] = __float2half(W[i]);
}

// ---------------------------------------------------------------------------
// Kernel 2a: QKV (256 CTAs x 32 rows) + mark needed rowsum rows
// ---------------------------------------------------------------------------
#define LJ 68

__global__ __launch_bounds__(256) void qkv_kernel(
    const int*   __restrict__ traj,
    const float* __restrict__ emb_t,
    const float* __restrict__ emb_l,
    const float* __restrict__ emb_u,
    const float* __restrict__ Wq,
    const float* __restrict__ Wk,
    const float* __restrict__ Wv)
{
    __shared__ float joint[32 * LJ];
    __shared__ float Ws[64 * LJ];

    const int tid = threadIdx.x;
    const int r0  = blockIdx.x * 32;

    for (int i = tid; i < 32 * 64; i += 256) {
        int m = i >> 6, d = i & 63;
        int base = (r0 + m) * 3;
        int u   = traj[base + 0];
        int loc = traj[base + 1];
        int t   = traj[base + 2];
        int ti  = (t - 1) % HOURS_C + 1;
        if (d == 0) g_need[loc - 1] = 1;
        joint[m * LJ + d] = emb_t[ti * DB + d] + emb_l[loc * DB + d] + emb_u[u * DB + d];
    }

    const int ty = tid >> 5;
    const int tx = tid & 31;
    const float* Wmats[3] = {Wq, Wk, Wv};
    float* outs[3] = {g_q, g_k, g_v};

#pragma unroll 1
    for (int w = 0; w < 3; w++) {
        __syncthreads();
        for (int i = tid; i < 64 * 16; i += 256) {
            int rr = i >> 4, c4 = i & 15;
            *(float4*)&Ws[rr * LJ + c4 * 4] = ((const float4*)Wmats[w])[i];
        }
        __syncthreads();

        float acc[4][2] = {};
#pragma unroll
        for (int j4 = 0; j4 < 16; j4++) {
            float4 b0 = *(const float4*)&Ws[tx * LJ + j4 * 4];
            float4 b1 = *(const float4*)&Ws[(tx + 32) * LJ + j4 * 4];
#pragma unroll
            for (int i = 0; i < 4; i++) {
                float4 a = *(const float4*)&joint[(ty * 4 + i) * LJ + j4 * 4];
                acc[i][0] += a.x * b0.x + a.y * b0.y + a.z * b0.z + a.w * b0.w;
                acc[i][1] += a.x * b1.x + a.y * b1.y + a.z * b1.z + a.w * b1.w;
            }
        }
        float* op = outs[w] + (size_t)(r0 + ty * 4) * DB;
#pragma unroll
        for (int i = 0; i < 4; i++) {
            op[i * DB + tx]      = acc[i][0];
            op[i * DB + tx + 32] = acc[i][1];
        }
    }
}

// ---------------------------------------------------------------------------
// Kernel 2b: scores + softmax + attn@v + delta2 -> X (fp16)
// grid (8, 64): blockIdx.y = n, blockIdx.x = 16-row m-tile. 256 threads.
// ---------------------------------------------------------------------------
#define LSC 132
#define MT 16

extern __shared__ float sm_s[];

__global__ __launch_bounds__(256) void scores_kernel(
    const int*   __restrict__ traj,
    const float* __restrict__ mat1,
    const float* __restrict__ vec,
    const int*   __restrict__ traj_len,
    const float* __restrict__ emb_su,
    const float* __restrict__ emb_sl,
    const float* __restrict__ emb_tu,
    const float* __restrict__ emb_tl)
{
    float* qs   = sm_s;                    // [MT][LJ]
    float* ks   = qs + MT * LJ;            // [128][LJ]
    float* vs   = ks + 128 * LJ;           // [128][LJ]
    float* sc   = vs + 128 * LJ;           // [MT][LSC]
    float* scal = sc + MT * LSC;           // 8

    const int n   = blockIdx.y;
    const int m0  = blockIdx.x * MT;
    const int tid = threadIdx.x;
    const int len = traj_len[n];

    if (tid < 8) {
        int which = tid >> 1, row = tid & 1;
        const float* e = (which == 0) ? emb_sl : (which == 1) ? emb_su
                       : (which == 2) ? emb_tl : emb_tu;
        float s = 0.f;
#pragma unroll
        for (int d = 0; d < DB; d++) s += e[row * DB + d];
        scal[tid] = s;
    }

    {
        const float4* gq = (const float4*)(g_q + (size_t)(n * MB + m0) * DB);
        for (int i = tid; i < MT * 16; i += 256) {
            int rr = i >> 4, c4 = i & 15;
            *(float4*)&qs[rr * LJ + c4 * 4] = gq[i];
        }
        const float4* gk = (const float4*)(g_k + (size_t)n * MB * DB);
        const float4* gv = (const float4*)(g_v + (size_t)n * MB * DB);
        for (int i = tid; i < 128 * 16; i += 256) {
            int rr = i >> 4, c4 = i & 15;
            *(float4*)&ks[rr * LJ + c4 * 4] = gk[i];
            *(float4*)&vs[rr * LJ + c4 * 4] = gv[i];
        }
    }
    __syncthreads();

    const int ty = tid >> 5;      // 2 m-rows each
    const int tx = tid & 31;

    // ---- scores MTx128 ----
    {
        float acc[2][4] = {};
#pragma unroll
        for (int j4 = 0; j4 < 16; j4++) {
            float4 b[4];
#pragma unroll
            for (int pp = 0; pp < 4; pp++)
                b[pp] = *(const float4*)&ks[(tx + pp * 32) * LJ + j4 * 4];
#pragma unroll
            for (int i = 0; i < 2; i++) {
                float4 a = *(const float4*)&qs[(ty * 2 + i) * LJ + j4 * 4];
#pragma unroll
                for (int pp = 0; pp < 4; pp++)
                    acc[i][pp] += a.x * b[pp].x + a.y * b[pp].y + a.z * b[pp].z + a.w * b[pp].w;
            }
        }
        float s0 = scal[0], s1 = scal[1], s2 = scal[2], s3 = scal[3];
        float s4 = scal[4], s5 = scal[5], s6 = scal[6], s7 = scal[7];
#pragma unroll
        for (int i = 0; i < 2; i++) {
            int mg = m0 + ty * 2 + i;
            bool vm = mg < len;
            const float2* mrow = (const float2*)mat1 + (size_t)(n * MB + mg) * MB;
#pragma unroll
            for (int pp = 0; pp < 4; pp++) {
                int p = tx + pp * 32;
                bool msk = vm && (p < len);
                float2 dd = mrow[p];
                float ssl = msk ? s1 : s0;
                float ssu = msk ? s3 : s2;
                float stl = msk ? s5 : s4;
                float stu = msk ? s7 : s6;
                float delta = (ssl * (100.0f - dd.x) + ssu * dd.x) * 0.01f
                            + (stl * (500.0f - dd.y) + stu * dd.y) * 0.002f;
                sc[(ty * 2 + i) * LSC + p] = acc[i][pp] + delta;
            }
        }
    }
    __syncthreads();

    // ---- softmax + ragged mask ----
    {
        int wid = tid >> 5, lane = tid & 31;
        for (int m2 = wid; m2 < MT; m2 += 8) {
            float v0 = sc[m2 * LSC + lane];
            float v1 = sc[m2 * LSC + lane + 32];
            float v2 = sc[m2 * LSC + lane + 64];
            float v3 = sc[m2 * LSC + lane + 96];
            float mx = fmaxf(fmaxf(v0, v1), fmaxf(v2, v3));
#pragma unroll
            for (int o = 16; o; o >>= 1) mx = fmaxf(mx, __shfl_xor_sync(~0u, mx, o));
            float e0 = __expf(v0 - mx), e1 = __expf(v1 - mx);
            float e2 = __expf(v2 - mx), e3 = __expf(v3 - mx);
            float sum = e0 + e1 + e2 + e3;
#pragma unroll
            for (int o = 16; o; o >>= 1) sum += __shfl_xor_sync(~0u, sum, o);
            float inv = 1.0f / sum;
            bool vm2 = (m0 + m2) < len;
            sc[m2 * LSC + lane]      = (vm2 && (lane      < len)) ? e0 * inv : 0.f;
            sc[m2 * LSC + lane + 32] = (vm2 && (lane + 32 < len)) ? e1 * inv : 0.f;
            sc[m2 * LSC + lane + 64] = (vm2 && (lane + 64 < len)) ? e2 * inv : 0.f;
            sc[m2 * LSC + lane + 96] = (vm2 && (lane + 96 < len)) ? e3 * inv : 0.f;
        }
    }
    __syncthreads();

    // ---- attn @ v (MTx64) + delta2 + fp16 store ----
    {
        float acc[2][2] = {};
#pragma unroll
        for (int p4 = 0; p4 < 32; p4++) {
            float b0[4], b1[4];
#pragma unroll
            for (int r = 0; r < 4; r++) {
                b0[r] = vs[(p4 * 4 + r) * LJ + tx];
                b1[r] = vs[(p4 * 4 + r) * LJ + tx + 32];
            }
#pragma unroll
            for (int i = 0; i < 2; i++) {
                float4 a = *(const float4*)&sc[(ty * 2 + i) * LSC + p4 * 4];
                acc[i][0] += a.x * b0[0] + a.y * b0[1] + a.z * b0[2] + a.w * b0[3];
                acc[i][1] += a.x * b1[0] + a.y * b1[1] + a.z * b1[2] + a.w * b1[3];
            }
        }
#pragma unroll
        for (int i = 0; i < 2; i++) {
            int mg = m0 + ty * 2 + i;
            bool vm = mg < len;
            int m1 = vm ? 1 : 0;
            int loc = traj[(n * MB + mg) * 3 + 1];
            float ds_sum = vm ? g_rowsum[loc - 1] : 0.f;
            float ve = vec[n * MB + mg];
            const float Lf = 8192.0f;
            float S_vsl = ds_sum;
            float S_vsu = 100.0f * Lf - ds_sum;
            float S_vtl = ve * Lf;
            float S_vtu = (500.0f - ve) * Lf;
            size_t base = (size_t)(n * MB + mg) * DB;
#pragma unroll
            for (int dd = 0; dd < 2; dd++) {
                int d = tx + dd * 32;
                float d2 = (emb_sl[m1 * DB + d] * S_vsu + emb_su[m1 * DB + d] * S_vsl) * 0.01f
                         + (emb_tl[m1 * DB + d] * S_vtu + emb_tu[m1 * DB + d] * S_vtl) * 0.002f;
                g_Xh[base + d] = __float2half(acc[i][dd] * d2);
            }
        }
    }
}

// ---------------------------------------------------------------------------
// Kernel 3: single-pass fp16 GEMM via mma.sync. 128x128 tile/CTA, 8 warps.
// ---------------------------------------------------------------------------
#define SA 72
#define TILE_HB (128 * SA)

extern __shared__ __align__(16) __half sm_g[];

__global__ __launch_bounds__(256) void out_gemm_mma(
    const float* __restrict__ b_out, float* __restrict__ out)
{
    __half* Ah = sm_g;
    __half* Bh = Ah + TILE_HB;
    float* sbias = (float*)(Bh + TILE_HB);

    const int tid  = threadIdx.x;
    const int wid  = tid >> 5;
    const int lane = tid & 31;
    const int wm   = wid & 1;
    const int wn   = wid >> 1;
    const int rB = blockIdx.y * 128;
    const int lB = blockIdx.x * 128;

    {
        const uint4* gA = (const uint4*)(g_Xh + (size_t)rB * DB);
        const uint4* gB = (const uint4*)(g_Wh + (size_t)lB * DB);
#pragma unroll
        for (int it = 0; it < 4; it++) {
            int idx = it * 256 + tid;
            int row = idx >> 3, ch = idx & 7;
            int so = row * SA + ch * 8;
            *(uint4*)(Ah + so) = gA[idx];
            *(uint4*)(Bh + so) = gB[idx];
        }
        if (tid < 128) sbias[tid] = b_out[lB + tid];
    }
    __syncthreads();

    const uint32_t sb = smem_u32(sm_g);
    const uint32_t aH = sb;
    const uint32_t bH = sb + TILE_HB * 2;

    const int lrow = lane & 15;
    const int lcol = (lane >> 4) * 8;

    float acc[4][4][4];
#pragma unroll
    for (int i = 0; i < 4; i++)
#pragma unroll
        for (int j = 0; j < 4; j++)
#pragma unroll
            for (int c = 0; c < 4; c++) acc[i][j][c] = 0.f;

#pragma unroll
    for (int ks = 0; ks < 4; ks++) {
        const uint32_t koff = (uint32_t)(ks * 16 + lcol) * 2;
        uint32_t fA[4][4];
#pragma unroll
        for (int mt = 0; mt < 4; mt++) {
            uint32_t ro = (uint32_t)((wm * 64 + mt * 16 + lrow) * SA) * 2 + koff;
            ldsm_x4(fA[mt], aH + ro);
        }
        uint32_t fB[2][4];
#pragma unroll
        for (int nt2 = 0; nt2 < 2; nt2++) {
            uint32_t ro = (uint32_t)((wn * 32 + nt2 * 16 + lrow) * SA) * 2 + koff;
            ldsm_x4(fB[nt2], bH + ro);
        }
#pragma unroll
        for (int mt = 0; mt < 4; mt++)
#pragma unroll
            for (int nt = 0; nt < 4; nt++) {
                const int h = nt >> 1, o = nt & 1;
                mma16816(acc[mt][nt], fA[mt], fB[h][o], fB[h][o + 2]);
            }
    }

    const int gr = lane >> 2;
    const int gc = (lane & 3) * 2;
#pragma unroll
    for (int mt = 0; mt < 4; mt++) {
#pragma unroll
        for (int nt = 0; nt < 4; nt++) {
            int col = wn * 32 + nt * 8 + gc;
            float b0 = sbias[col], b1 = sbias[col + 1];
            size_t r0 = (size_t)(rB + wm * 64 + mt * 16 + gr) * LB + lB + col;
            float2 v0 = {acc[mt][nt][0] + b0, acc[mt][nt][1] + b1};
            float2 v1 = {acc[mt][nt][2] + b0, acc[mt][nt][3] + b1};
            *(float2*)(out + r0)          = v0;
            *(float2*)(out + r0 + 8 * LB) = v1;
        }
    }
}

// ---------------------------------------------------------------------------
extern "C" void kernel_launch(void* const* d_in, const int* in_sizes, int n_in,
                              void* d_out, int out_size) {
    const int*   traj     = (const int*)  d_in[0];
    const float* mat1     = (const float*)d_in[1];
    const float* mat2s    = (const float*)d_in[2];
    const float* vec      = (const float*)d_in[3];
    const int*   traj_len = (const int*)  d_in[4];
    const float* emb_t    = (const float*)d_in[5];
    const float* emb_l    = (const float*)d_in[6];
    const float* emb_u    = (const float*)d_in[7];
    const float* emb_su   = (const float*)d_in[8];
    const float* emb_sl   = (const float*)d_in[9];
    const float* emb_tu   = (const float*)d_in[10];
    const float* emb_tl   = (const float*)d_in[11];
    const float* Wq       = (const float*)d_in[12];
    const float* Wk       = (const float*)d_in[13];
    const float* Wv       = (const float*)d_in[14];
    const float* W_out    = (const float*)d_in[15];
    const float* b_out    = (const float*)d_in[16];
    float* out = (float*)d_out;

    const int SC_SMEM = (MT * LJ + 128 * LJ + 128 * LJ + MT * LSC + 8) * (int)sizeof(float);
    const int GEMM_SMEM = (2 * TILE_HB) * 2 + 128 * (int)sizeof(float);
    cudaFuncSetAttribute(scores_kernel, cudaFuncAttributeMaxDynamicSharedMemorySize, SC_SMEM);
    cudaFuncSetAttribute(out_gemm_mma,  cudaFuncAttributeMaxDynamicSharedMemorySize, GEMM_SMEM);

    zero_flags_kernel<<<LB / (256 * 16), 256>>>();
    wsplit_kernel<<<(LB * DB) / 256, 256>>>(W_out);
    qkv_kernel<<<(NB * MB) / 32, 256>>>(traj, emb_t, emb_l, emb_u, Wq, Wk, Wv);
    rowsum_kernel<<<LB, 256>>>(mat2s);
    dim3 sg(MB / MT, NB);
    scores_kernel<<<sg, 256, SC_SMEM>>>(traj, mat1, vec, traj_len,
                                        emb_su, emb_sl, emb_tu, emb_tl);
    dim3 grid(LB / 128, (NB * MB) / 128);
    out_gemm_mma<<<grid, 256, GEMM_SMEM>>>(b_out, out);
}